// round 16
// baseline (speedup 1.0000x reference)
#include <cuda_runtime.h>
#include <cuda_fp16.h>

// ---------------------------------------------------------------------------
// SemanticActor v13 = v12 with A1 double-buffered h: ONE sync per pair
// (was two) and cross-warp overlap of GEMM2(p) with GEMM1/epi1(p+1).
//  A0 (grid=ntiles): Wc staged, XFS gather, C-GEMMs -> C' (fp32, gC).
//  A1 (grid=148, persistent): WUV+W2 staged ONCE; per tile: XOBJ gather,
//     6-pair loop (h double-buffered), dump agg fp16 h-image -> gAggH[t].
//  B  (grid=148, persistent): RHO staged ONCE; per tile: copy gAggH -> h_s,
//     GEMM3, fused bias/relu/fp16-round + head partials in registers.
// ---------------------------------------------------------------------------

__constant__ int cFIRST[20]  = {0,1,2,3,4,5,6,7,8,9,10,11,12,13,15,16,17,20,21,25};
__constant__ int cSECOND[20] = {0,1,2,3,4,5,6,7,8,9,14,18,19,22,23,24,26,27,28,29};
__constant__ int cPI[6] = {0,0,1,1,2,2};
__constant__ int cPJ[6] = {1,2,0,2,0,1};
__constant__ int cPF[6] = {1,1,0,1,0,0};

// Pre-transposed padded fp16 weights [n][k]:
__device__ __align__(16) __half gWct[256 * 72];    // W1[0:50] pad k->72
__device__ __align__(16) __half gWUVt[256 * 40];   // W1[50:65]@k0..15, W1[65:80]@k16..31
__device__ __align__(16) __half gW2t[256 * 264];   // phi_w2
__device__ __align__(16) __half gRHOt[256 * 264];  // rho_w1

// fp32 C' scratch (C + b1), fragment order: [variant][tile*1024+tid][16 floats].
#define CS_OFF 16777216ull
__device__ __align__(16) float gC[2 * 16777216ull];
// agg (post-relu pair sum) as fp16 h-image per tile: 64 rows x 264 stride.
__device__ __align__(16) __half gAggH[1024ull * 16896ull];

#define NTHREADS 1024
#define NSM 148

__global__ void convert_weights_kernel(const float* __restrict__ w1,
                                       const float* __restrict__ w2,
                                       const float* __restrict__ rho) {
    int idx = blockIdx.x * blockDim.x + threadIdx.x;
    if (idx >= 256 * 256) return;
    int k = idx >> 8;
    int n = idx & 255;
    gW2t[n * 264 + k]  = __float2half_rn(w2[idx]);   // w2[k*256+n]
    gRHOt[n * 264 + k] = __float2half_rn(rho[idx]);
    if (k < 72)
        gWct[n * 72 + k] = __float2half_rn(k < 50 ? w1[k * 256 + n] : 0.f);
    if (k < 40) {
        float v = 0.f;
        if (k < 16)      { if (k < 15)      v = w1[(50 + k) * 256 + n]; }
        else if (k < 32) { if (k - 16 < 15) v = w1[(65 + (k - 16)) * 256 + n]; }
        gWUVt[n * 40 + k] = __float2half_rn(v);
    }
}

__device__ __forceinline__ void mma16816(float c[4],
                                         unsigned a0, unsigned a1, unsigned a2, unsigned a3,
                                         unsigned b0, unsigned b1) {
    asm volatile(
        "mma.sync.aligned.m16n8k16.row.col.f32.f16.f16.f32 "
        "{%0,%1,%2,%3},{%4,%5,%6,%7},{%8,%9},{%0,%1,%2,%3};"
        : "+f"(c[0]), "+f"(c[1]), "+f"(c[2]), "+f"(c[3])
        : "r"(a0), "r"(a1), "r"(a2), "r"(a3), "r"(b0), "r"(b1));
}

__device__ __forceinline__ void ldsm4(unsigned& r0, unsigned& r1, unsigned& r2, unsigned& r3,
                                      unsigned addr) {
    asm volatile("ldmatrix.sync.aligned.m8n8.x4.shared.b16 {%0,%1,%2,%3}, [%4];"
                 : "=r"(r0), "=r"(r1), "=r"(r2), "=r"(r3) : "r"(addr));
}

// Warp-tile GEMM 16x32: acc += A[16 x 16*KSTEPS] * Wt^T
template <int KSTEPS>
__device__ __forceinline__ void gemm_tile(unsigned aAddr, const unsigned bAddr[2],
                                          float acc[4][4]) {
#pragma unroll
    for (int ks = 0; ks < KSTEPS; ++ks) {
        unsigned a0, a1, a2, a3;
        ldsm4(a0, a1, a2, a3, aAddr + ks * 32);
#pragma unroll
        for (int j = 0; j < 2; ++j) {
            unsigned b0, b1, b2, b3;
            ldsm4(b0, b1, b2, b3, bAddr[j] + ks * 32);
            mma16816(acc[2 * j],     a0, a1, a2, a3, b0, b1);
            mma16816(acc[2 * j + 1], a0, a1, a2, a3, b2, b3);
        }
    }
}

#define ZACC(a) \
    _Pragma("unroll") for (int nt = 0; nt < 4; ++nt) { a[nt][0]=0.f; a[nt][1]=0.f; a[nt][2]=0.f; a[nt][3]=0.f; }

// round to fp16 and back (matches the SMEM round-trip numerics)
__device__ __forceinline__ float r16(float x) {
    return __half2float(__float2half_rn(x));
}

// ======================= A0: C' prep =======================
// SMEM: XFS 0..17408 ; Wc 17408..54272 ; b1 54272..55296
#define A0_SMEM 55296
__global__ void __launch_bounds__(NTHREADS, 1)
prep_kernel(const float* __restrict__ obs, const float* __restrict__ ag,
            const float* __restrict__ g, const float* __restrict__ b1g, int B) {
    extern __shared__ char smem[];
    __half* xfs_s  = (__half*)(smem);
    float*  bias_s = (float*)(smem + 54272);

    const int tid  = threadIdx.x;
    const int lane = tid & 31;
    const int warp = tid >> 5;
    const int wm = warp >> 3, wn = warp & 7;
    const int q  = lane & 3;
    const int row0 = wm * 16, col0 = wn * 32;
    const int rowbase = blockIdx.x * 64;

    const int aRow = (lane & 7) + ((lane >> 3) & 1) * 8;
    const int aK   = (lane >> 4) * 8;
    const int bN   = (lane >> 4) * 8 + (lane & 7);
    const int bK   = ((lane >> 3) & 1) * 8;

    const unsigned xfs_sh = (unsigned)__cvta_generic_to_shared(smem);
    const unsigned wc_sh  = (unsigned)__cvta_generic_to_shared(smem + 17408);
    const unsigned aXf = xfs_sh + ((row0 + aRow) * 136 + aK) * 2;
    const unsigned aXs = aXf + 64 * 2;
    unsigned bWc[2];
#pragma unroll
    for (int j = 0; j < 2; ++j)
        bWc[j] = wc_sh + ((col0 + j * 16 + bN) * 72 + bK) * 2;

    for (int e = tid; e < 64 * 128; e += NTHREADS) {
        int rr = e >> 7, c = e & 127;
        int cc = c & 63;
        const int* sel = (c < 64) ? cFIRST : cSECOND;
        int gr = rowbase + rr;
        float v = 0.f;
        if (gr < B && cc < 50) {
            if (cc < 20)      v = ag[gr * 30 + sel[cc]];
            else if (cc < 30) v = obs[gr * 55 + (cc - 20)];
            else              v = g[gr * 30 + sel[cc - 30]];
        }
        xfs_s[rr * 136 + c] = __float2half_rn(v);
    }
    {
        const uint4* s = (const uint4*)gWct;
        uint4* d = (uint4*)(smem + 17408);
        for (int i = tid; i < 256 * 72 * 2 / 16; i += NTHREADS) d[i] = s[i];
    }
    for (int i = tid; i < 256; i += NTHREADS) bias_s[i] = b1g[i];
    __syncthreads();

    const size_t slot = (size_t)blockIdx.x * NTHREADS + tid;
    float4* cF = reinterpret_cast<float4*>(gC + slot * 16);
    float4* cS = reinterpret_cast<float4*>(gC + CS_OFF + slot * 16);

    float acc[4][4];
    ZACC(acc)
    gemm_tile<4>(aXf, bWc, acc);
#pragma unroll
    for (int nt = 0; nt < 4; ++nt) {
        const int cb = col0 + nt * 8 + q * 2;
        const float bx = bias_s[cb], by = bias_s[cb + 1];
        cF[nt] = make_float4(acc[nt][0] + bx, acc[nt][1] + by,
                             acc[nt][2] + bx, acc[nt][3] + by);
    }
    ZACC(acc)
    gemm_tile<4>(aXs, bWc, acc);
#pragma unroll
    for (int nt = 0; nt < 4; ++nt) {
        const int cb = col0 + nt * 8 + q * 2;
        const float bx = bias_s[cb], by = bias_s[cb + 1];
        cS[nt] = make_float4(acc[nt][0] + bx, acc[nt][1] + by,
                             acc[nt][2] + bx, acc[nt][3] + by);
    }
}

// ======================= A1: persistent pair loop, double-buffered h ========
// SMEM: XOBJ 0..7168 ; WUV 7168..27648 ; W2 27648..162816 ;
//       h0 162816..196608 ; h1 196608..230400 ; b2 230400..231424
#define A1_SMEM 231424
__global__ void __launch_bounds__(NTHREADS, 1)
actor_kernel(const float* __restrict__ obs, const float* __restrict__ b2g,
             int B, int ntiles) {
    extern __shared__ char smem[];
    __half* xobj_s = (__half*)(smem);
    float*  bias_s = (float*)(smem + 230400);

    const int tid  = threadIdx.x;
    const int lane = tid & 31;
    const int warp = tid >> 5;
    const int wm = warp >> 3, wn = warp & 7;
    const int r  = lane >> 2, q = lane & 3;
    const int row0 = wm * 16, col0 = wn * 32;

    const int aRow = (lane & 7) + ((lane >> 3) & 1) * 8;
    const int aK   = (lane >> 4) * 8;
    const int bN   = (lane >> 4) * 8 + (lane & 7);
    const int bK   = ((lane >> 3) & 1) * 8;

    const unsigned xobj_sh = (unsigned)__cvta_generic_to_shared(smem);
    const unsigned wuv_sh  = (unsigned)__cvta_generic_to_shared(smem + 7168);
    const unsigned w2_sh   = (unsigned)__cvta_generic_to_shared(smem + 27648);
    const unsigned h0_sh   = (unsigned)__cvta_generic_to_shared(smem + 162816);
    const unsigned h1_sh   = (unsigned)__cvta_generic_to_shared(smem + 196608);

    __half* hbuf[2] = { (__half*)(smem + 162816), (__half*)(smem + 196608) };

    const unsigned aObjBase = xobj_sh + ((row0 + aRow) * 56 + aK) * 2;
    const unsigned aHoff = ((row0 + aRow) * 264 + aK) * 2;
    const unsigned aH[2] = { h0_sh + aHoff, h1_sh + aHoff };
    unsigned bWUV[2], bW2[2];
#pragma unroll
    for (int j = 0; j < 2; ++j) {
        bWUV[j] = wuv_sh + ((col0 + j * 16 + bN) * 40  + bK) * 2;
        bW2[j]  = w2_sh  + ((col0 + j * 16 + bN) * 264 + bK) * 2;
    }

    // stage WUV + W2 + b2 ONCE
    {
        const uint4* su = (const uint4*)gWUVt;
        uint4* du = (uint4*)(smem + 7168);
        for (int i = tid; i < 256 * 40 * 2 / 16; i += NTHREADS) du[i] = su[i];
        const uint4* s2 = (const uint4*)gW2t;
        uint4* d2 = (uint4*)(smem + 27648);
        for (int i = tid; i < 256 * 264 * 2 / 16; i += NTHREADS) d2[i] = s2[i];
    }
    for (int i = tid; i < 256; i += NTHREADS) bias_s[i] = b2g[i];

    float acc[4][4], agg[4][4];

    for (int t = blockIdx.x; t < ntiles; t += gridDim.x) {
        const int rowbase = t * 64;
        // gather XOBJ (all warps have finished prior tile's GEMM1 by loop entry)
        for (int e = tid; e < 64 * 48; e += NTHREADS) {
            int rr = e / 48, c = e - rr * 48;
            int o = c >> 4, ci = c & 15;
            int gr = rowbase + rr;
            float v = (gr < B && ci < 15) ? obs[gr * 55 + 10 + 15 * o + ci] : 0.f;
            xobj_s[rr * 56 + 16 * o + ci] = __float2half_rn(v);
        }
        const size_t slot = (size_t)t * NTHREADS + tid;
        const float4* cF = reinterpret_cast<const float4*>(gC + slot * 16);
        const float4* cS = reinterpret_cast<const float4*>(gC + CS_OFF + slot * 16);
#pragma unroll
        for (int nt = 0; nt < 4; ++nt) { agg[nt][0]=0.f; agg[nt][1]=0.f; agg[nt][2]=0.f; agg[nt][3]=0.f; }
        __syncthreads();   // XOBJ ready (also: all warps past prior tile entirely)

#pragma unroll
        for (int p = 0; p < 6; ++p) {
            const int buf = p & 1;
            const int i_ = cPI[p], j_ = cPJ[p];
            const float4* cp = cPF[p] ? cF : cS;
            // acc := C'
#pragma unroll
            for (int nt = 0; nt < 4; ++nt) {
                float4 v = cp[nt];
                acc[nt][0] = v.x; acc[nt][1] = v.y; acc[nt][2] = v.z; acc[nt][3] = v.w;
            }
            // GEMM1: acc += obj_i @ WU + obj_j @ WV
            gemm_tile<1>(aObjBase + 32 * i_, bWUV, acc);
            {
                unsigned bV[2];
#pragma unroll
                for (int j = 0; j < 2; ++j) bV[j] = bWUV[j] + 32;
                gemm_tile<1>(aObjBase + 32 * j_, bV, acc);
            }
            // epilogue1 -> h buffer (p&1). Safe: last reader of this buffer was
            // GEMM2(p-2); every warp passed sync(p-1) which requires it done.
            __half* hw = hbuf[buf];
#pragma unroll
            for (int nt = 0; nt < 4; ++nt) {
                const int cb = col0 + nt * 8 + q * 2;
                __half2 v01 = __floats2half2_rn(fmaxf(acc[nt][0], 0.f), fmaxf(acc[nt][1], 0.f));
                __half2 v23 = __floats2half2_rn(fmaxf(acc[nt][2], 0.f), fmaxf(acc[nt][3], 0.f));
                *(__half2*)&hw[(row0 + r)     * 264 + cb] = v01;
                *(__half2*)&hw[(row0 + r + 8) * 264 + cb] = v23;
            }
            __syncthreads();   // h[buf] ready (single sync per pair)

            // GEMM2: acc = h[buf] @ W2 (K=256); agg += relu(acc + b2)
            ZACC(acc)
            gemm_tile<16>(aH[buf], bW2, acc);
#pragma unroll
            for (int nt = 0; nt < 4; ++nt) {
                const int cb = col0 + nt * 8 + q * 2;
                const float bx = bias_s[cb], by = bias_s[cb + 1];
                agg[nt][0] += fmaxf(acc[nt][0] + bx, 0.f);
                agg[nt][1] += fmaxf(acc[nt][1] + by, 0.f);
                agg[nt][2] += fmaxf(acc[nt][2] + bx, 0.f);
                agg[nt][3] += fmaxf(acc[nt][3] + by, 0.f);
            }
        }

        // dump agg (fp16) to global h-image
        __half* ah = gAggH + (size_t)t * 16896;
#pragma unroll
        for (int nt = 0; nt < 4; ++nt) {
            const int cb = col0 + nt * 8 + q * 2;
            *(__half2*)&ah[(row0 + r)     * 264 + cb] = __floats2half2_rn(agg[nt][0], agg[nt][1]);
            *(__half2*)&ah[(row0 + r + 8) * 264 + cb] = __floats2half2_rn(agg[nt][2], agg[nt][3]);
        }
        __syncthreads();   // all warps done with this tile's buffers before next gather
    }
}

// ======================= B: GEMM3 + register-side heads =======================
// SMEM: h 0..33792 ; RHO 33792..168960 ; hw2 168960..177152 ([n][8] f32) ;
//       part 177152..193536 ([wn][64][8] f32) ; b3 193536..194560
#define B_SMEM 194560
__global__ void __launch_bounds__(NTHREADS, 1)
out_kernel(const float* __restrict__ mean_w, const float* __restrict__ mean_b,
           const float* __restrict__ logstd_w, const float* __restrict__ logstd_b,
           const float* __restrict__ b3g, float* __restrict__ out,
           int B, int ntiles) {
    extern __shared__ char smem[];
    __half* h_s    = (__half*)(smem);
    float*  hw2_s  = (float*)(smem + 168960);
    float*  part_s = (float*)(smem + 177152);
    float*  bias_s = (float*)(smem + 193536);

    const int tid  = threadIdx.x;
    const int lane = tid & 31;
    const int warp = tid >> 5;
    const int wm = warp >> 3, wn = warp & 7;
    const int r  = lane >> 2, q = lane & 3;
    const int row0 = wm * 16, col0 = wn * 32;

    const int aRow = (lane & 7) + ((lane >> 3) & 1) * 8;
    const int aK   = (lane >> 4) * 8;
    const int bN   = (lane >> 4) * 8 + (lane & 7);
    const int bK   = ((lane >> 3) & 1) * 8;

    const unsigned h_sh   = (unsigned)__cvta_generic_to_shared(smem);
    const unsigned rho_sh = (unsigned)__cvta_generic_to_shared(smem + 33792);
    const unsigned aH = h_sh + ((row0 + aRow) * 264 + aK) * 2;
    unsigned bRHO[2];
#pragma unroll
    for (int j = 0; j < 2; ++j)
        bRHO[j] = rho_sh + ((col0 + j * 16 + bN) * 264 + bK) * 2;

    // stage RHO + head weights ([n][8]: mean 0..3 | logstd 4..7) + b3 ONCE
    {
        const uint4* s2 = (const uint4*)gRHOt;
        uint4* d2 = (uint4*)(smem + 33792);
        for (int i = tid; i < 256 * 264 * 2 / 16; i += NTHREADS) d2[i] = s2[i];
    }
    for (int i = tid; i < 2048; i += NTHREADS) {
        int n = i >> 3, o = i & 7;
        hw2_s[i] = (o < 4) ? mean_w[n * 4 + o] : logstd_w[n * 4 + (o - 4)];
    }
    for (int i = tid; i < 256; i += NTHREADS) bias_s[i] = b3g[i];
    __syncthreads();

    float acc[4][4];

    for (int t = blockIdx.x; t < ntiles; t += gridDim.x) {
        const int rowbase = t * 64;
        {
            const uint4* s = (const uint4*)(gAggH + (size_t)t * 16896);
            uint4* d = (uint4*)smem;
            for (int i = tid; i < 16896 * 2 / 16; i += NTHREADS) d[i] = s[i];
        }
        __syncthreads();

        // GEMM3: acc = agg @ rho (K=256)
        ZACC(acc)
        gemm_tile<16>(aH, bRHO, acc);

        // fused epilogue3 + head partials, all in registers
        float ps[2][8];
#pragma unroll
        for (int m = 0; m < 2; ++m)
#pragma unroll
            for (int o = 0; o < 8; ++o) ps[m][o] = 0.f;
#pragma unroll
        for (int nt = 0; nt < 4; ++nt) {
            const int cb = col0 + nt * 8 + q * 2;
            const float bx = bias_s[cb], by = bias_s[cb + 1];
            const float v0 = r16(fmaxf(acc[nt][0] + bx, 0.f));
            const float v1 = r16(fmaxf(acc[nt][1] + by, 0.f));
            const float v2 = r16(fmaxf(acc[nt][2] + bx, 0.f));
            const float v3 = r16(fmaxf(acc[nt][3] + by, 0.f));
            const float4 wA0 = *(const float4*)&hw2_s[cb * 8];
            const float4 wA1 = *(const float4*)&hw2_s[cb * 8 + 4];
            const float4 wB0 = *(const float4*)&hw2_s[(cb + 1) * 8];
            const float4 wB1 = *(const float4*)&hw2_s[(cb + 1) * 8 + 4];
            ps[0][0] += v0 * wA0.x + v1 * wB0.x;  ps[0][1] += v0 * wA0.y + v1 * wB0.y;
            ps[0][2] += v0 * wA0.z + v1 * wB0.z;  ps[0][3] += v0 * wA0.w + v1 * wB0.w;
            ps[0][4] += v0 * wA1.x + v1 * wB1.x;  ps[0][5] += v0 * wA1.y + v1 * wB1.y;
            ps[0][6] += v0 * wA1.z + v1 * wB1.z;  ps[0][7] += v0 * wA1.w + v1 * wB1.w;
            ps[1][0] += v2 * wA0.x + v3 * wB0.x;  ps[1][1] += v2 * wA0.y + v3 * wB0.y;
            ps[1][2] += v2 * wA0.z + v3 * wB0.z;  ps[1][3] += v2 * wA0.w + v3 * wB0.w;
            ps[1][4] += v2 * wA1.x + v3 * wB1.x;  ps[1][5] += v2 * wA1.y + v3 * wB1.y;
            ps[1][6] += v2 * wA1.z + v3 * wB1.z;  ps[1][7] += v2 * wA1.w + v3 * wB1.w;
        }
#pragma unroll
        for (int m = 0; m < 2; ++m)
#pragma unroll
            for (int o = 0; o < 8; ++o) {
                ps[m][o] += __shfl_xor_sync(0xffffffffu, ps[m][o], 1);
                ps[m][o] += __shfl_xor_sync(0xffffffffu, ps[m][o], 2);
            }
        if (q == 0) {
#pragma unroll
            for (int o = 0; o < 8; ++o) {
                part_s[wn * 512 + (row0 + r) * 8 + o]     = ps[0][o];
                part_s[wn * 512 + (row0 + r + 8) * 8 + o] = ps[1][o];
            }
        }
        __syncthreads();

        if (tid < 512) {
            const int row = tid >> 3;
            const int o = tid & 7;
            const int head = o >> 2;
            const int j = o & 3;
            float s = 0.f;
#pragma unroll
            for (int w8 = 0; w8 < 8; ++w8) s += part_s[w8 * 512 + row * 8 + o];
            s += head ? logstd_b[j] : mean_b[j];
            if (head) s = fminf(fmaxf(s, -20.f), 2.f);
            const int gr = rowbase + row;
            if (gr < B) out[(head ? (size_t)B * 4 : (size_t)0) + (size_t)gr * 4 + j] = s;
        }
        __syncthreads();
    }
}

extern "C" void kernel_launch(void* const* d_in, const int* in_sizes, int n_in,
                              void* d_out, int out_size) {
    const float* obs = (const float*)d_in[0];
    const float* ag  = (const float*)d_in[1];
    const float* g   = (const float*)d_in[2];
    const float* w1  = (const float*)d_in[3];
    const float* b1  = (const float*)d_in[4];
    const float* w2  = (const float*)d_in[5];
    const float* b2  = (const float*)d_in[6];
    const float* rho = (const float*)d_in[7];
    const float* b3  = (const float*)d_in[8];
    const float* mw  = (const float*)d_in[9];
    const float* mb  = (const float*)d_in[10];
    const float* lw  = (const float*)d_in[11];
    const float* lb  = (const float*)d_in[12];
    float* out = (float*)d_out;
    const int B = in_sizes[0] / 55;
    const int ntiles = (B + 63) / 64;

    convert_weights_kernel<<<(256 * 256 + 255) / 256, 256>>>(w1, w2, rho);

    cudaFuncSetAttribute(prep_kernel,  cudaFuncAttributeMaxDynamicSharedMemorySize, A0_SMEM);
    cudaFuncSetAttribute(actor_kernel, cudaFuncAttributeMaxDynamicSharedMemorySize, A1_SMEM);
    cudaFuncSetAttribute(out_kernel,   cudaFuncAttributeMaxDynamicSharedMemorySize, B_SMEM);

    prep_kernel<<<ntiles, NTHREADS, A0_SMEM>>>(obs, ag, g, b1, B);
    actor_kernel<<<NSM, NTHREADS, A1_SMEM>>>(obs, b2, B, ntiles);
    out_kernel<<<NSM, NTHREADS, B_SMEM>>>(mw, mb, lw, lb, b3, out, B, ntiles);
}

// round 17
// speedup vs baseline: 1.0639x; 1.0639x over previous
#include <cuda_runtime.h>
#include <cuda_fp16.h>

// ---------------------------------------------------------------------------
// SemanticActor v14 = v12 (best: 411us) + cp.async double-buffered gAggH
// prefetch in out_kernel (overlap tile t+148 copy with tile t GEMM3/heads).
//  A0 (grid=ntiles): Wc staged, XFS gather, C-GEMMs -> C' (fp32, gC).
//  A1 (grid=148, persistent): WUV+W2 staged ONCE; per tile: XOBJ gather,
//     6-pair loop (agg in regs), dump agg fp16 h-image -> gAggH[t].
//  B  (grid=148, persistent): RHO staged ONCE; per tile: cp.async h, GEMM3,
//     fused bias/relu/fp16-round + head partials in registers.
// ---------------------------------------------------------------------------

__constant__ int cFIRST[20]  = {0,1,2,3,4,5,6,7,8,9,10,11,12,13,15,16,17,20,21,25};
__constant__ int cSECOND[20] = {0,1,2,3,4,5,6,7,8,9,14,18,19,22,23,24,26,27,28,29};
__constant__ int cPI[6] = {0,0,1,1,2,2};
__constant__ int cPJ[6] = {1,2,0,2,0,1};
__constant__ int cPF[6] = {1,1,0,1,0,0};

// Pre-transposed padded fp16 weights [n][k]:
__device__ __align__(16) __half gWct[256 * 72];    // W1[0:50] pad k->72
__device__ __align__(16) __half gWUVt[256 * 40];   // W1[50:65]@k0..15, W1[65:80]@k16..31
__device__ __align__(16) __half gW2t[256 * 264];   // phi_w2
__device__ __align__(16) __half gRHOt[256 * 264];  // rho_w1

// fp32 C' scratch (C + b1), fragment order: [variant][tile*1024+tid][16 floats].
#define CS_OFF 16777216ull
__device__ __align__(16) float gC[2 * 16777216ull];
// agg (post-relu pair sum) as fp16 h-image per tile: 64 rows x 264 stride.
__device__ __align__(16) __half gAggH[1024ull * 16896ull];

#define NTHREADS 1024
#define NSM 148

__global__ void convert_weights_kernel(const float* __restrict__ w1,
                                       const float* __restrict__ w2,
                                       const float* __restrict__ rho) {
    int idx = blockIdx.x * blockDim.x + threadIdx.x;
    if (idx >= 256 * 256) return;
    int k = idx >> 8;
    int n = idx & 255;
    gW2t[n * 264 + k]  = __float2half_rn(w2[idx]);   // w2[k*256+n]
    gRHOt[n * 264 + k] = __float2half_rn(rho[idx]);
    if (k < 72)
        gWct[n * 72 + k] = __float2half_rn(k < 50 ? w1[k * 256 + n] : 0.f);
    if (k < 40) {
        float v = 0.f;
        if (k < 16)      { if (k < 15)      v = w1[(50 + k) * 256 + n]; }
        else if (k < 32) { if (k - 16 < 15) v = w1[(65 + (k - 16)) * 256 + n]; }
        gWUVt[n * 40 + k] = __float2half_rn(v);
    }
}

__device__ __forceinline__ void mma16816(float c[4],
                                         unsigned a0, unsigned a1, unsigned a2, unsigned a3,
                                         unsigned b0, unsigned b1) {
    asm volatile(
        "mma.sync.aligned.m16n8k16.row.col.f32.f16.f16.f32 "
        "{%0,%1,%2,%3},{%4,%5,%6,%7},{%8,%9},{%0,%1,%2,%3};"
        : "+f"(c[0]), "+f"(c[1]), "+f"(c[2]), "+f"(c[3])
        : "r"(a0), "r"(a1), "r"(a2), "r"(a3), "r"(b0), "r"(b1));
}

__device__ __forceinline__ void ldsm4(unsigned& r0, unsigned& r1, unsigned& r2, unsigned& r3,
                                      unsigned addr) {
    asm volatile("ldmatrix.sync.aligned.m8n8.x4.shared.b16 {%0,%1,%2,%3}, [%4];"
                 : "=r"(r0), "=r"(r1), "=r"(r2), "=r"(r3) : "r"(addr));
}

// Warp-tile GEMM 16x32: acc += A[16 x 16*KSTEPS] * Wt^T
template <int KSTEPS>
__device__ __forceinline__ void gemm_tile(unsigned aAddr, const unsigned bAddr[2],
                                          float acc[4][4]) {
#pragma unroll
    for (int ks = 0; ks < KSTEPS; ++ks) {
        unsigned a0, a1, a2, a3;
        ldsm4(a0, a1, a2, a3, aAddr + ks * 32);
#pragma unroll
        for (int j = 0; j < 2; ++j) {
            unsigned b0, b1, b2, b3;
            ldsm4(b0, b1, b2, b3, bAddr[j] + ks * 32);
            mma16816(acc[2 * j],     a0, a1, a2, a3, b0, b1);
            mma16816(acc[2 * j + 1], a0, a1, a2, a3, b2, b3);
        }
    }
}

#define ZACC(a) \
    _Pragma("unroll") for (int nt = 0; nt < 4; ++nt) { a[nt][0]=0.f; a[nt][1]=0.f; a[nt][2]=0.f; a[nt][3]=0.f; }

// round to fp16 and back (matches the SMEM round-trip numerics)
__device__ __forceinline__ float r16(float x) {
    return __half2float(__float2half_rn(x));
}

#define CP_ASYNC16(saddr, gptr) \
    asm volatile("cp.async.cg.shared.global [%0], [%1], 16;" \
                 :: "r"(saddr), "l"(gptr) : "memory")
#define CP_COMMIT() asm volatile("cp.async.commit_group;" ::: "memory")
#define CP_WAIT0() asm volatile("cp.async.wait_group 0;" ::: "memory")
#define CP_WAIT1() asm volatile("cp.async.wait_group 1;" ::: "memory")

// ======================= A0: C' prep =======================
// SMEM: XFS 0..17408 ; Wc 17408..54272 ; b1 54272..55296
#define A0_SMEM 55296
__global__ void __launch_bounds__(NTHREADS, 1)
prep_kernel(const float* __restrict__ obs, const float* __restrict__ ag,
            const float* __restrict__ g, const float* __restrict__ b1g, int B) {
    extern __shared__ char smem[];
    __half* xfs_s  = (__half*)(smem);
    float*  bias_s = (float*)(smem + 54272);

    const int tid  = threadIdx.x;
    const int lane = tid & 31;
    const int warp = tid >> 5;
    const int wm = warp >> 3, wn = warp & 7;
    const int q  = lane & 3;
    const int row0 = wm * 16, col0 = wn * 32;
    const int rowbase = blockIdx.x * 64;

    const int aRow = (lane & 7) + ((lane >> 3) & 1) * 8;
    const int aK   = (lane >> 4) * 8;
    const int bN   = (lane >> 4) * 8 + (lane & 7);
    const int bK   = ((lane >> 3) & 1) * 8;

    const unsigned xfs_sh = (unsigned)__cvta_generic_to_shared(smem);
    const unsigned wc_sh  = (unsigned)__cvta_generic_to_shared(smem + 17408);
    const unsigned aXf = xfs_sh + ((row0 + aRow) * 136 + aK) * 2;
    const unsigned aXs = aXf + 64 * 2;
    unsigned bWc[2];
#pragma unroll
    for (int j = 0; j < 2; ++j)
        bWc[j] = wc_sh + ((col0 + j * 16 + bN) * 72 + bK) * 2;

    for (int e = tid; e < 64 * 128; e += NTHREADS) {
        int rr = e >> 7, c = e & 127;
        int cc = c & 63;
        const int* sel = (c < 64) ? cFIRST : cSECOND;
        int gr = rowbase + rr;
        float v = 0.f;
        if (gr < B && cc < 50) {
            if (cc < 20)      v = ag[gr * 30 + sel[cc]];
            else if (cc < 30) v = obs[gr * 55 + (cc - 20)];
            else              v = g[gr * 30 + sel[cc - 30]];
        }
        xfs_s[rr * 136 + c] = __float2half_rn(v);
    }
    {
        const uint4* s = (const uint4*)gWct;
        uint4* d = (uint4*)(smem + 17408);
        for (int i = tid; i < 256 * 72 * 2 / 16; i += NTHREADS) d[i] = s[i];
    }
    for (int i = tid; i < 256; i += NTHREADS) bias_s[i] = b1g[i];
    __syncthreads();

    const size_t slot = (size_t)blockIdx.x * NTHREADS + tid;
    float4* cF = reinterpret_cast<float4*>(gC + slot * 16);
    float4* cS = reinterpret_cast<float4*>(gC + CS_OFF + slot * 16);

    float acc[4][4];
    ZACC(acc)
    gemm_tile<4>(aXf, bWc, acc);
#pragma unroll
    for (int nt = 0; nt < 4; ++nt) {
        const int cb = col0 + nt * 8 + q * 2;
        const float bx = bias_s[cb], by = bias_s[cb + 1];
        cF[nt] = make_float4(acc[nt][0] + bx, acc[nt][1] + by,
                             acc[nt][2] + bx, acc[nt][3] + by);
    }
    ZACC(acc)
    gemm_tile<4>(aXs, bWc, acc);
#pragma unroll
    for (int nt = 0; nt < 4; ++nt) {
        const int cb = col0 + nt * 8 + q * 2;
        const float bx = bias_s[cb], by = bias_s[cb + 1];
        cS[nt] = make_float4(acc[nt][0] + bx, acc[nt][1] + by,
                             acc[nt][2] + bx, acc[nt][3] + by);
    }
}

// ======================= A1: persistent pair loop (v12, unchanged) ==========
// SMEM: XOBJ 0..7168 ; WUV 7168..27648 ; W2 27648..162816 ; h 162816..196608 ;
//       b2 196608..197632
#define A1_SMEM 197632
__global__ void __launch_bounds__(NTHREADS, 1)
actor_kernel(const float* __restrict__ obs, const float* __restrict__ b2g,
             int B, int ntiles) {
    extern __shared__ char smem[];
    __half* xobj_s = (__half*)(smem);
    __half* h_s    = (__half*)(smem + 162816);
    float*  bias_s = (float*)(smem + 196608);

    const int tid  = threadIdx.x;
    const int lane = tid & 31;
    const int warp = tid >> 5;
    const int wm = warp >> 3, wn = warp & 7;
    const int r  = lane >> 2, q = lane & 3;
    const int row0 = wm * 16, col0 = wn * 32;

    const int aRow = (lane & 7) + ((lane >> 3) & 1) * 8;
    const int aK   = (lane >> 4) * 8;
    const int bN   = (lane >> 4) * 8 + (lane & 7);
    const int bK   = ((lane >> 3) & 1) * 8;

    const unsigned xobj_sh = (unsigned)__cvta_generic_to_shared(smem);
    const unsigned wuv_sh  = (unsigned)__cvta_generic_to_shared(smem + 7168);
    const unsigned w2_sh   = (unsigned)__cvta_generic_to_shared(smem + 27648);
    const unsigned h_sh    = (unsigned)__cvta_generic_to_shared(smem + 162816);

    const unsigned aObjBase = xobj_sh + ((row0 + aRow) * 56 + aK) * 2;
    const unsigned aH = h_sh + ((row0 + aRow) * 264 + aK) * 2;
    unsigned bWUV[2], bW2[2];
#pragma unroll
    for (int j = 0; j < 2; ++j) {
        bWUV[j] = wuv_sh + ((col0 + j * 16 + bN) * 40  + bK) * 2;
        bW2[j]  = w2_sh  + ((col0 + j * 16 + bN) * 264 + bK) * 2;
    }

    // stage WUV + W2 + b2 ONCE
    {
        const uint4* su = (const uint4*)gWUVt;
        uint4* du = (uint4*)(smem + 7168);
        for (int i = tid; i < 256 * 40 * 2 / 16; i += NTHREADS) du[i] = su[i];
        const uint4* s2 = (const uint4*)gW2t;
        uint4* d2 = (uint4*)(smem + 27648);
        for (int i = tid; i < 256 * 264 * 2 / 16; i += NTHREADS) d2[i] = s2[i];
    }
    for (int i = tid; i < 256; i += NTHREADS) bias_s[i] = b2g[i];

    float acc[4][4], agg[4][4];

    for (int t = blockIdx.x; t < ntiles; t += gridDim.x) {
        const int rowbase = t * 64;
        for (int e = tid; e < 64 * 48; e += NTHREADS) {
            int rr = e / 48, c = e - rr * 48;
            int o = c >> 4, ci = c & 15;
            int gr = rowbase + rr;
            float v = (gr < B && ci < 15) ? obs[gr * 55 + 10 + 15 * o + ci] : 0.f;
            xobj_s[rr * 56 + 16 * o + ci] = __float2half_rn(v);
        }
        const size_t slot = (size_t)t * NTHREADS + tid;
        const float4* cF = reinterpret_cast<const float4*>(gC + slot * 16);
        const float4* cS = reinterpret_cast<const float4*>(gC + CS_OFF + slot * 16);
#pragma unroll
        for (int nt = 0; nt < 4; ++nt) { agg[nt][0]=0.f; agg[nt][1]=0.f; agg[nt][2]=0.f; agg[nt][3]=0.f; }
        __syncthreads();   // XOBJ ready; all warps' previous GEMM2 complete

        for (int p = 0; p < 6; ++p) {
            const int i_ = cPI[p], j_ = cPJ[p];
            const float4* cp = cPF[p] ? cF : cS;
#pragma unroll
            for (int nt = 0; nt < 4; ++nt) {
                float4 v = cp[nt];
                acc[nt][0] = v.x; acc[nt][1] = v.y; acc[nt][2] = v.z; acc[nt][3] = v.w;
            }
            gemm_tile<1>(aObjBase + 32 * i_, bWUV, acc);
            {
                unsigned bV[2];
#pragma unroll
                for (int j = 0; j < 2; ++j) bV[j] = bWUV[j] + 32;
                gemm_tile<1>(aObjBase + 32 * j_, bV, acc);
            }
            __syncthreads();   // previous GEMM2 reads of h done

#pragma unroll
            for (int nt = 0; nt < 4; ++nt) {
                const int cb = col0 + nt * 8 + q * 2;
                __half2 v01 = __floats2half2_rn(fmaxf(acc[nt][0], 0.f), fmaxf(acc[nt][1], 0.f));
                __half2 v23 = __floats2half2_rn(fmaxf(acc[nt][2], 0.f), fmaxf(acc[nt][3], 0.f));
                *(__half2*)&h_s[(row0 + r)     * 264 + cb] = v01;
                *(__half2*)&h_s[(row0 + r + 8) * 264 + cb] = v23;
            }
            __syncthreads();   // h ready

            ZACC(acc)
            gemm_tile<16>(aH, bW2, acc);
#pragma unroll
            for (int nt = 0; nt < 4; ++nt) {
                const int cb = col0 + nt * 8 + q * 2;
                const float bx = bias_s[cb], by = bias_s[cb + 1];
                agg[nt][0] += fmaxf(acc[nt][0] + bx, 0.f);
                agg[nt][1] += fmaxf(acc[nt][1] + by, 0.f);
                agg[nt][2] += fmaxf(acc[nt][2] + bx, 0.f);
                agg[nt][3] += fmaxf(acc[nt][3] + by, 0.f);
            }
        }

        // dump agg (fp16) to global h-image
        __half* ah = gAggH + (size_t)t * 16896;
#pragma unroll
        for (int nt = 0; nt < 4; ++nt) {
            const int cb = col0 + nt * 8 + q * 2;
            *(__half2*)&ah[(row0 + r)     * 264 + cb] = __floats2half2_rn(agg[nt][0], agg[nt][1]);
            *(__half2*)&ah[(row0 + r + 8) * 264 + cb] = __floats2half2_rn(agg[nt][2], agg[nt][3]);
        }
    }
}

// ============== B: GEMM3 + register heads, cp.async double-buffered h =======
// SMEM: h0 0..33792 ; h1 33792..67584 ; RHO 67584..202752 ;
//       hw2 202752..210944 ([n][8] f32) ; part 210944..227328 ; b3 227328..228352
#define B_SMEM 228352
__global__ void __launch_bounds__(NTHREADS, 1)
out_kernel(const float* __restrict__ mean_w, const float* __restrict__ mean_b,
           const float* __restrict__ logstd_w, const float* __restrict__ logstd_b,
           const float* __restrict__ b3g, float* __restrict__ out,
           int B, int ntiles) {
    extern __shared__ char smem[];
    float*  hw2_s  = (float*)(smem + 202752);
    float*  part_s = (float*)(smem + 210944);
    float*  bias_s = (float*)(smem + 227328);

    const int tid  = threadIdx.x;
    const int lane = tid & 31;
    const int warp = tid >> 5;
    const int wm = warp >> 3, wn = warp & 7;
    const int r  = lane >> 2, q = lane & 3;
    const int row0 = wm * 16, col0 = wn * 32;

    const int aRow = (lane & 7) + ((lane >> 3) & 1) * 8;
    const int aK   = (lane >> 4) * 8;
    const int bN   = (lane >> 4) * 8 + (lane & 7);
    const int bK   = ((lane >> 3) & 1) * 8;

    const unsigned smem_sh = (unsigned)__cvta_generic_to_shared(smem);
    const unsigned rho_sh  = smem_sh + 67584;
    const unsigned aHoff = ((row0 + aRow) * 264 + aK) * 2;
    const unsigned aH[2] = { smem_sh + aHoff, smem_sh + 33792 + aHoff };
    unsigned bRHO[2];
#pragma unroll
    for (int j = 0; j < 2; ++j)
        bRHO[j] = rho_sh + ((col0 + j * 16 + bN) * 264 + bK) * 2;

    // stage RHO + head weights ([n][8]: mean 0..3 | logstd 4..7) + b3 ONCE
    {
        const uint4* s2 = (const uint4*)gRHOt;
        uint4* d2 = (uint4*)(smem + 67584);
        for (int i = tid; i < 256 * 264 * 2 / 16; i += NTHREADS) d2[i] = s2[i];
    }
    for (int i = tid; i < 2048; i += NTHREADS) {
        int n = i >> 3, o = i & 7;
        hw2_s[i] = (o < 4) ? mean_w[n * 4 + o] : logstd_w[n * 4 + (o - 4)];
    }
    for (int i = tid; i < 256; i += NTHREADS) bias_s[i] = b3g[i];

    // prefetch first tile into buf 0
    int t0 = blockIdx.x;
    if (t0 < ntiles) {
        const char* src = (const char*)(gAggH + (size_t)t0 * 16896);
        for (int i = tid; i < 2112; i += NTHREADS)
            CP_ASYNC16(smem_sh + i * 16, src + i * 16);
    }
    CP_COMMIT();

    float acc[4][4];
    int buf = 0;

    for (int t = t0; t < ntiles; t += gridDim.x) {
        const int rowbase = t * 64;
        const int tn = t + gridDim.x;
        // prefetch next tile into the other buffer (its readers finished last iter)
        if (tn < ntiles) {
            const char* src = (const char*)(gAggH + (size_t)tn * 16896);
            const unsigned dst = smem_sh + (buf ^ 1) * 33792;
            for (int i = tid; i < 2112; i += NTHREADS)
                CP_ASYNC16(dst + i * 16, src + i * 16);
            CP_COMMIT();
            CP_WAIT1();   // current buffer's group complete; next still in flight
        } else {
            CP_WAIT0();
        }
        __syncthreads();  // all threads see current h buffer

        // GEMM3: acc = agg @ rho (K=256)
        ZACC(acc)
        gemm_tile<16>(aH[buf], bRHO, acc);

        // fused epilogue3 + head partials, all in registers
        float ps[2][8];
#pragma unroll
        for (int m = 0; m < 2; ++m)
#pragma unroll
            for (int o = 0; o < 8; ++o) ps[m][o] = 0.f;
#pragma unroll
        for (int nt = 0; nt < 4; ++nt) {
            const int cb = col0 + nt * 8 + q * 2;
            const float bx = bias_s[cb], by = bias_s[cb + 1];
            const float v0 = r16(fmaxf(acc[nt][0] + bx, 0.f));
            const float v1 = r16(fmaxf(acc[nt][1] + by, 0.f));
            const float v2 = r16(fmaxf(acc[nt][2] + bx, 0.f));
            const float v3 = r16(fmaxf(acc[nt][3] + by, 0.f));
            const float4 wA0 = *(const float4*)&hw2_s[cb * 8];
            const float4 wA1 = *(const float4*)&hw2_s[cb * 8 + 4];
            const float4 wB0 = *(const float4*)&hw2_s[(cb + 1) * 8];
            const float4 wB1 = *(const float4*)&hw2_s[(cb + 1) * 8 + 4];
            ps[0][0] += v0 * wA0.x + v1 * wB0.x;  ps[0][1] += v0 * wA0.y + v1 * wB0.y;
            ps[0][2] += v0 * wA0.z + v1 * wB0.z;  ps[0][3] += v0 * wA0.w + v1 * wB0.w;
            ps[0][4] += v0 * wA1.x + v1 * wB1.x;  ps[0][5] += v0 * wA1.y + v1 * wB1.y;
            ps[0][6] += v0 * wA1.z + v1 * wB1.z;  ps[0][7] += v0 * wA1.w + v1 * wB1.w;
            ps[1][0] += v2 * wA0.x + v3 * wB0.x;  ps[1][1] += v2 * wA0.y + v3 * wB0.y;
            ps[1][2] += v2 * wA0.z + v3 * wB0.z;  ps[1][3] += v2 * wA0.w + v3 * wB0.w;
            ps[1][4] += v2 * wA1.x + v3 * wB1.x;  ps[1][5] += v2 * wA1.y + v3 * wB1.y;
            ps[1][6] += v2 * wA1.z + v3 * wB1.z;  ps[1][7] += v2 * wA1.w + v3 * wB1.w;
        }
#pragma unroll
        for (int m = 0; m < 2; ++m)
#pragma unroll
            for (int o = 0; o < 8; ++o) {
                ps[m][o] += __shfl_xor_sync(0xffffffffu, ps[m][o], 1);
                ps[m][o] += __shfl_xor_sync(0xffffffffu, ps[m][o], 2);
            }
        if (q == 0) {
#pragma unroll
            for (int o = 0; o < 8; ++o) {
                part_s[wn * 512 + (row0 + r) * 8 + o]     = ps[0][o];
                part_s[wn * 512 + (row0 + r + 8) * 8 + o] = ps[1][o];
            }
        }
        __syncthreads();

        if (tid < 512) {
            const int row = tid >> 3;
            const int o = tid & 7;
            const int head = o >> 2;
            const int j = o & 3;
            float s = 0.f;
#pragma unroll
            for (int w8 = 0; w8 < 8; ++w8) s += part_s[w8 * 512 + row * 8 + o];
            s += head ? logstd_b[j] : mean_b[j];
            if (head) s = fminf(fmaxf(s, -20.f), 2.f);
            const int gr = rowbase + row;
            if (gr < B) out[(head ? (size_t)B * 4 : (size_t)0) + (size_t)gr * 4 + j] = s;
        }
        __syncthreads();  // reads of h[buf]/part done before its next overwrite
        buf ^= 1;
    }
}

extern "C" void kernel_launch(void* const* d_in, const int* in_sizes, int n_in,
                              void* d_out, int out_size) {
    const float* obs = (const float*)d_in[0];
    const float* ag  = (const float*)d_in[1];
    const float* g   = (const float*)d_in[2];
    const float* w1  = (const float*)d_in[3];
    const float* b1  = (const float*)d_in[4];
    const float* w2  = (const float*)d_in[5];
    const float* b2  = (const float*)d_in[6];
    const float* rho = (const float*)d_in[7];
    const float* b3  = (const float*)d_in[8];
    const float* mw  = (const float*)d_in[9];
    const float* mb  = (const float*)d_in[10];
    const float* lw  = (const float*)d_in[11];
    const float* lb  = (const float*)d_in[12];
    float* out = (float*)d_out;
    const int B = in_sizes[0] / 55;
    const int ntiles = (B + 63) / 64;

    convert_weights_kernel<<<(256 * 256 + 255) / 256, 256>>>(w1, w2, rho);

    cudaFuncSetAttribute(prep_kernel,  cudaFuncAttributeMaxDynamicSharedMemorySize, A0_SMEM);
    cudaFuncSetAttribute(actor_kernel, cudaFuncAttributeMaxDynamicSharedMemorySize, A1_SMEM);
    cudaFuncSetAttribute(out_kernel,   cudaFuncAttributeMaxDynamicSharedMemorySize, B_SMEM);

    prep_kernel<<<ntiles, NTHREADS, A0_SMEM>>>(obs, ag, g, b1, B);
    actor_kernel<<<NSM, NTHREADS, A1_SMEM>>>(obs, b2, B, ntiles);
    out_kernel<<<NSM, NTHREADS, B_SMEM>>>(mw, mb, lw, lb, b3, out, B, ntiles);
}